// round 7
// baseline (speedup 1.0000x reference)
#include <cuda_runtime.h>
#include <math.h>

// Problem constants (fixed by the reference)
#define N_K        16
#define C_CAT      136          // 16*17/2 upper-tri pairs
#define C_PAD      160          // padded to 32*5 for a uniform unrolled loop
#define DIM        64
#define MU_PITCH   68           // DIM + 4 pad: keeps rows 16B-aligned (68*4=272=17*16)
#define NROWS      8192         // 512 * 16
#define ROWS_PER_BLK 8
#define MAIN_BLOCKS (NROWS / ROWS_PER_BLK)   // 1024

#define LOG2PI_F   1.8378770664093453f
#define LN2_F      0.6931471805599453f
// Phi-tanh approx: Phi(x) ~= 0.5*(1+tanh(C1*x + C3*x^3))
#define PHI_C1     0.7978845608028654f
#define PHI_C3     0.03567740813712f

// ---- device scratch (static globals; no allocation) ----
__device__ float4 d_c4[C_PAD];   // {k1, 0.5*mB2, recip, s=sqrt(clip_is)}
__device__ float2 d_cb[C_PAD];   // {base, bitcast(A | B<<8)}
__device__ float  d_partials[MAIN_BLOCKS];
__device__ unsigned int d_counter = 0;

__device__ __forceinline__ float tanh_approx(float x) {
    float r; asm("tanh.approx.f32 %0, %1;" : "=f"(r) : "f"(x)); return r;
}

// ---------------------------------------------------------------------------
// Kernel 1: per-category constants. 17 blocks x 256 thr; one WARP per category.
// Diagonal pairs encoded as heavy categories (k1=0, recip=0 -> nu=0; s=20 ->
// tanh(u1)=1, tanh(u2)=0 -> D=1; base=lp). Slots [136,160) are padding.
// ---------------------------------------------------------------------------
__global__ __launch_bounds__(256) void precompute_kernel(const float* __restrict__ pi,
                                                         const float* __restrict__ mu)
{
    const int t = threadIdx.x;
    const int w = t >> 5, l = t & 31;

    if (blockIdx.x == 0 && t >= C_CAT && t < C_PAD) {
        d_c4[t] = make_float4(0.f, 0.f, 0.f, 20.f);
        d_cb[t] = make_float2(-1e30f, __int_as_float(0));
    }

    // warp-local softmax denominator over the 136 logits
    float v0 = pi[l], v1 = pi[l + 32], v2 = pi[l + 64], v3 = pi[l + 96];
    float v4 = (l < 8) ? pi[128 + l] : -INFINITY;
    float mx = fmaxf(fmaxf(fmaxf(v0, v1), fmaxf(v2, v3)), v4);
    #pragma unroll
    for (int o = 16; o; o >>= 1) mx = fmaxf(mx, __shfl_xor_sync(0xffffffffu, mx, o));
    float sm = __expf(v0 - mx) + __expf(v1 - mx) + __expf(v2 - mx) + __expf(v3 - mx)
             + ((l < 8) ? __expf(v4 - mx) : 0.f);
    #pragma unroll
    for (int o = 16; o; o >>= 1) sm += __shfl_xor_sync(0xffffffffu, sm, o);

    const int c = blockIdx.x * 8 + w;          // category index (< 136 always)

    int A = 0, rem = c;
    while (rem >= (N_K - A)) { rem -= (N_K - A); ++A; }
    const int B = A + rem;

    float invsig = 0.f, k1 = 0.f, mB2 = 0.f;
    #pragma unroll
    for (int h = 0; h < 2; ++h) {
        const int d = l + h * 32;
        const float mb = mu[d * N_K + B];
        const float ma = mu[d * N_K + A];
        const float a  = mb - ma;
        invsig = fmaf(a, a, invsig);
        k1     = fmaf(a, mb, k1);
        mB2    = fmaf(mb, mb, mB2);
    }
    #pragma unroll
    for (int o = 16; o; o >>= 1) {
        invsig += __shfl_xor_sync(0xffffffffu, invsig, o);
        k1     += __shfl_xor_sync(0xffffffffu, k1, o);
        mB2    += __shfl_xor_sync(0xffffffffu, mB2, o);
    }

    if (l == 0) {
        const float e  = __expf(pi[c] - mx);
        const float tp = fminf(fmaxf(e / sm, 1e-16f), 1.0f);
        const float lp = -32.0f * LOG2PI_F + logf(tp);

        float base, recip, s, k1s;
        if (A == B) {
            base = lp; recip = 0.f; s = 20.f; k1s = 0.f;
        } else {
            const float clip_is = fminf(fmaxf(invsig, 1e-12f), 1e30f);
            s     = sqrtf(clip_is);
            base  = lp + 0.5f * (LOG2PI_F - logf(clip_is)) - LN2_F;
            recip = 1.0f / invsig;
            k1s   = k1;
        }
        d_c4[c] = make_float4(k1s, 0.5f * mB2, recip, s);
        d_cb[c] = make_float2(base, __int_as_float(A | (B << 8)));
    }
}

// ---------------------------------------------------------------------------
// Kernel 2: main. 8 rows/block (256 thr), one warp per row.
// mu TRANSPOSED in smem -> vectorized g-dot (16 LDS.128 instead of 64 LDS.32).
// ---------------------------------------------------------------------------
__global__ __launch_bounds__(256, 6) void main_kernel(const float* __restrict__ z,
                                                      const float* __restrict__ mu,
                                                      float* __restrict__ out)
{
    __shared__ float  mu_t[N_K][MU_PITCH];          // 16 x 68 floats, transposed
    __shared__ float  z_s [ROWS_PER_BLK][DIM];      // 2 KB
    __shared__ float4 c4_s[C_PAD];                  // 2560 B
    __shared__ float2 cb_s[C_PAD];                  // 1280 B
    __shared__ float  rowres[ROWS_PER_BLK];
    __shared__ float  red[256];
    __shared__ int    s_is_last;

    const int t = threadIdx.x;

    // ---- stage: mu transposed (scalar), z vectorized, constants ----
    for (int i = t; i < DIM * N_K; i += 256) {
        const int d = i >> 4, k = i & 15;           // mu is [d][k], k fastest
        mu_t[k][d] = mu[i];
    }
    const int row0 = blockIdx.x * ROWS_PER_BLK;
    if (t < (ROWS_PER_BLK * DIM) / 4) {
        const float4* z4 = (const float4*)(z + row0 * DIM);
        ((float4*)&z_s[0][0])[t] = z4[t];
    }
    for (int i = t; i < C_PAD; i += 256) {
        c4_s[i] = d_c4[i];
        cb_s[i] = d_cb[i];
    }
    __syncthreads();

    const int w = t >> 5;        // warp == row within block
    const int l = t & 31;

    // 0.5*|z|^2 (scalar LDS + butterfly; off the critical path)
    float p = z_s[w][l] * z_s[w][l] + z_s[w][l + 32] * z_s[w][l + 32];
    #pragma unroll
    for (int o = 16; o; o >>= 1) p += __shfl_xor_sync(0xffffffffu, p, o);
    const float z2h = 0.5f * p;

    // g_k = dot(z_row, mu_k): lane (k=l&15, h=l>>4) does dims [32h,32h+32)
    // via 8 float4 pairs with 4 ILP accumulators, then folds halves.
    float gval;
    {
        const int k = l & 15, h = l >> 4;
        const float4* zr = (const float4*)&z_s[w][h * 32];
        const float4* mr = (const float4*)&mu_t[k][h * 32];
        float a0 = 0.f, a1 = 0.f, a2 = 0.f, a3 = 0.f;
        #pragma unroll
        for (int j = 0; j < 8; ++j) {
            const float4 zv = zr[j];
            const float4 mv = mr[j];
            a0 = fmaf(zv.x, mv.x, a0);
            a1 = fmaf(zv.y, mv.y, a1);
            a2 = fmaf(zv.z, mv.z, a2);
            a3 = fmaf(zv.w, mv.w, a3);
        }
        float acc = (a0 + a1) + (a2 + a3);
        acc += __shfl_xor_sync(0xffffffffu, acc, 16);
        gval = acc;              // lane l and l+16 both hold g_{l&15}
    }

    // ---- uniform hot loop: 5 categories per lane, fully unrolled ----
    float qv[5], Dv[5];
    float m = -INFINITY;
    #pragma unroll
    for (int i = 0; i < 5; ++i) {
        const int c = l + 32 * i;
        const float4 q4 = c4_s[c];                  // k1, 0.5*mB2, recip, s
        const float2 b2 = cb_s[c];
        const int ab = __float_as_int(b2.y);
        const float gA = __shfl_sync(0xffffffffu, gval, ab & 15);
        const float gB = __shfl_sync(0xffffffffu, gval, (ab >> 8) & 15);
        const float hbsq  = (z2h - gB) + q4.y;      // 0.5 * beta_sq
        const float delta = (q4.x - gB) + gA;
        const float nu    = delta * q4.z;
        const float qq    = fmaf(0.5f * delta, nu, -hbsq) + b2.x;
        qv[i] = qq;
        m = fmaxf(m, qq);
        const float ns   = nu * q4.w;
        const float eta1 = q4.w - ns;
        const float eta2 = -ns;
        const float u1 = eta1 * fmaf(PHI_C3, eta1 * eta1, PHI_C1);
        const float u2 = eta2 * fmaf(PHI_C3, eta2 * eta2, PHI_C1);
        Dv[i] = fmaxf(tanh_approx(u1) - tanh_approx(u2), 2e-16f);
    }

    // warp max of q
    #pragma unroll
    for (int o = 16; o; o >>= 1) m = fmaxf(m, __shfl_xor_sync(0xffffffffu, m, o));

    // ssum = sum exp(q - m) * D
    float ssum = 0.f;
    #pragma unroll
    for (int i = 0; i < 5; ++i) ssum = fmaf(__expf(qv[i] - m), Dv[i], ssum);

    #pragma unroll
    for (int o = 16; o; o >>= 1) ssum += __shfl_xor_sync(0xffffffffu, ssum, o);

    if (l == 0) rowres[w] = m + __logf(ssum);
    __syncthreads();

    // ---- per-block partial + last-block-done finalize ----
    if (t == 0) {
        float s = 0.f;
        #pragma unroll
        for (int r = 0; r < ROWS_PER_BLK; ++r) s += rowres[r];
        d_partials[blockIdx.x] = s;
        __threadfence();
        const unsigned int ticket = atomicAdd(&d_counter, 1u);
        s_is_last = (ticket == (unsigned)(gridDim.x - 1));
    }
    __syncthreads();

    if (s_is_last) {
        volatile float* vp = d_partials;
        float s = 0.f;
        for (int i = t; i < MAIN_BLOCKS; i += 256) s += vp[i];
        red[t] = s; __syncthreads();
        for (int o = 128; o; o >>= 1) { if (t < o) red[t] += red[t + o]; __syncthreads(); }
        if (t == 0) {
            out[0] = red[0] * (1.0f / (float)NROWS);
            d_counter = 0;                 // reset for next graph replay
        }
    }
}

// ---------------------------------------------------------------------------
extern "C" void kernel_launch(void* const* d_in, const int* in_sizes, int n_in,
                              void* d_out, int out_size)
{
    (void)in_sizes; (void)n_in; (void)out_size;
    const float* z  = (const float*)d_in[0];
    const float* pi = (const float*)d_in[1];
    const float* mu = (const float*)d_in[2];
    float* out = (float*)d_out;

    precompute_kernel<<<17, 256>>>(pi, mu);
    main_kernel<<<MAIN_BLOCKS, 256>>>(z, mu, out);
}

// round 8
// speedup vs baseline: 1.0065x; 1.0065x over previous
#include <cuda_runtime.h>
#include <math.h>

// Problem constants (fixed by the reference)
#define N_K        16
#define C_CAT      136          // 16*17/2 upper-tri pairs
#define C_PAD      160          // padded to 32*5 for a uniform unrolled loop
#define DIM        64
#define MU_PITCH   68           // DIM + 4 pad: rows 16B-aligned (68*4 = 272)
#define NROWS      8192         // 512 * 16
#define ROWS_PER_BLK 8
#define MAIN_BLOCKS (NROWS / ROWS_PER_BLK)   // 1024

#define LOG2PI_F   1.8378770664093453f
#define LN2_F      0.6931471805599453f
// Phi-tanh approx: Phi(x) ~= 0.5*(1+tanh(C1*x + C3*x^3))
#define PHI_C1     0.7978845608028654f
#define PHI_C3     0.03567740813712f

// ---- device scratch (static globals; no allocation) ----
__device__ float4 d_c4[C_PAD];   // {k1, 0.5*mB2, recip, s=sqrt(clip_is)}
__device__ float2 d_cb[C_PAD];   // {base, bitcast(A | B<<8)}
__device__ float  d_partials[MAIN_BLOCKS];
__device__ unsigned int d_counter = 0;

__device__ __forceinline__ float tanh_approx(float x) {
    float r; asm("tanh.approx.f32 %0, %1;" : "=f"(r) : "f"(x)); return r;
}

// ---------------------------------------------------------------------------
// Kernel 1: per-category constants. 17 blocks x 256 thr; one WARP per category.
// Diagonal pairs encoded as heavy categories (k1=0, recip=0 -> nu=0; s=20 ->
// tanh(u1)=1, tanh(u2)=0 -> D=1; base=lp). Slots [136,160) are padding.
// ---------------------------------------------------------------------------
__global__ __launch_bounds__(256) void precompute_kernel(const float* __restrict__ pi,
                                                         const float* __restrict__ mu)
{
    const int t = threadIdx.x;
    const int w = t >> 5, l = t & 31;

    if (blockIdx.x == 0 && t >= C_CAT && t < C_PAD) {
        d_c4[t] = make_float4(0.f, 0.f, 0.f, 20.f);
        d_cb[t] = make_float2(-1e30f, __int_as_float(0));
    }

    // warp-local softmax denominator over the 136 logits
    float v0 = pi[l], v1 = pi[l + 32], v2 = pi[l + 64], v3 = pi[l + 96];
    float v4 = (l < 8) ? pi[128 + l] : -INFINITY;
    float mx = fmaxf(fmaxf(fmaxf(v0, v1), fmaxf(v2, v3)), v4);
    #pragma unroll
    for (int o = 16; o; o >>= 1) mx = fmaxf(mx, __shfl_xor_sync(0xffffffffu, mx, o));
    float sm = __expf(v0 - mx) + __expf(v1 - mx) + __expf(v2 - mx) + __expf(v3 - mx)
             + ((l < 8) ? __expf(v4 - mx) : 0.f);
    #pragma unroll
    for (int o = 16; o; o >>= 1) sm += __shfl_xor_sync(0xffffffffu, sm, o);

    const int c = blockIdx.x * 8 + w;          // category index (< 136 always)

    int A = 0, rem = c;
    while (rem >= (N_K - A)) { rem -= (N_K - A); ++A; }
    const int B = A + rem;

    float invsig = 0.f, k1 = 0.f, mB2 = 0.f;
    #pragma unroll
    for (int h = 0; h < 2; ++h) {
        const int d = l + h * 32;
        const float mb = mu[d * N_K + B];
        const float ma = mu[d * N_K + A];
        const float a  = mb - ma;
        invsig = fmaf(a, a, invsig);
        k1     = fmaf(a, mb, k1);
        mB2    = fmaf(mb, mb, mB2);
    }
    #pragma unroll
    for (int o = 16; o; o >>= 1) {
        invsig += __shfl_xor_sync(0xffffffffu, invsig, o);
        k1     += __shfl_xor_sync(0xffffffffu, k1, o);
        mB2    += __shfl_xor_sync(0xffffffffu, mB2, o);
    }

    if (l == 0) {
        const float e  = __expf(pi[c] - mx);
        const float tp = fminf(fmaxf(e / sm, 1e-16f), 1.0f);
        const float lp = -32.0f * LOG2PI_F + logf(tp);

        float base, recip, s, k1s;
        if (A == B) {
            base = lp; recip = 0.f; s = 20.f; k1s = 0.f;
        } else {
            const float clip_is = fminf(fmaxf(invsig, 1e-12f), 1e30f);
            s     = sqrtf(clip_is);
            base  = lp + 0.5f * (LOG2PI_F - logf(clip_is)) - LN2_F;
            recip = 1.0f / invsig;
            k1s   = k1;
        }
        d_c4[c] = make_float4(k1s, 0.5f * mB2, recip, s);
        d_cb[c] = make_float2(base, __int_as_float(A | (B << 8)));
    }
}

// ---------------------------------------------------------------------------
// Kernel 2: main. 8 rows/block (256 thr), one warp per row.
// NO register cap (ILP > occupancy for this latency-bound kernel).
// Constants hoisted to registers; z prefetched to registers at entry.
// ---------------------------------------------------------------------------
__global__ __launch_bounds__(256) void main_kernel(const float* __restrict__ z,
                                                   const float* __restrict__ mu,
                                                   float* __restrict__ out)
{
    __shared__ float  mu_t[N_K][MU_PITCH];          // transposed mu
    __shared__ float  z_s [ROWS_PER_BLK][DIM];
    __shared__ float4 c4_s[C_PAD];
    __shared__ float2 cb_s[C_PAD];
    __shared__ float  rowres[ROWS_PER_BLK];
    __shared__ float  red[256];
    __shared__ int    s_is_last;

    const int t = threadIdx.x;
    const int w = t >> 5;        // warp == row within block
    const int l = t & 31;

    // prefetch this warp's z elements into registers immediately (DRAM latency
    // starts now, hidden behind all the smem staging below)
    const int row0 = blockIdx.x * ROWS_PER_BLK;
    const float* zrow = z + (row0 + w) * DIM;
    const float zr0 = zrow[l];
    const float zr1 = zrow[l + 32];

    // ---- stage mu (transposed) and constants; barrier does NOT wait on z ----
    for (int i = t; i < DIM * N_K; i += 256) {
        const int d = i >> 4, k = i & 15;           // mu is [d][k]
        mu_t[k][d] = mu[i];
    }
    for (int i = t; i < C_PAD; i += 256) {
        c4_s[i] = d_c4[i];
        cb_s[i] = d_cb[i];
    }
    __syncthreads();

    // per-warp z staging (only this warp's row)
    z_s[w][l]      = zr0;
    z_s[w][l + 32] = zr1;
    __syncwarp();

    // hoist this lane's 5 category-constant sets into registers; their LDS
    // latency overlaps the z2/g-dot arithmetic below
    float4 c4r[5];
    float2 cbr[5];
    #pragma unroll
    for (int i = 0; i < 5; ++i) {
        c4r[i] = c4_s[l + 32 * i];
        cbr[i] = cb_s[l + 32 * i];
    }

    // 0.5*|z|^2 from the prefetched registers
    float p = zr0 * zr0 + zr1 * zr1;
    #pragma unroll
    for (int o = 16; o; o >>= 1) p += __shfl_xor_sync(0xffffffffu, p, o);
    const float z2h = 0.5f * p;

    // g_k = dot(z_row, mu_k): lane (k=l&15, h=l>>4) does dims [32h,32h+32)
    float gval;
    {
        const int k = l & 15, h = l >> 4;
        const float4* zr = (const float4*)&z_s[w][h * 32];
        const float4* mr = (const float4*)&mu_t[k][h * 32];
        float a0 = 0.f, a1 = 0.f, a2 = 0.f, a3 = 0.f;
        #pragma unroll
        for (int j = 0; j < 8; ++j) {
            const float4 zv = zr[j];
            const float4 mv = mr[j];
            a0 = fmaf(zv.x, mv.x, a0);
            a1 = fmaf(zv.y, mv.y, a1);
            a2 = fmaf(zv.z, mv.z, a2);
            a3 = fmaf(zv.w, mv.w, a3);
        }
        float acc = (a0 + a1) + (a2 + a3);
        acc += __shfl_xor_sync(0xffffffffu, acc, 16);
        gval = acc;              // lane l and l+16 both hold g_{l&15}
    }

    // ---- uniform hot loop: 5 independent category chains, all in registers ----
    float qv[5], Dv[5];
    float m = -INFINITY;
    #pragma unroll
    for (int i = 0; i < 5; ++i) {
        const float4 q4 = c4r[i];                   // k1, 0.5*mB2, recip, s
        const float2 b2 = cbr[i];
        const int ab = __float_as_int(b2.y);
        const float gA = __shfl_sync(0xffffffffu, gval, ab & 15);
        const float gB = __shfl_sync(0xffffffffu, gval, (ab >> 8) & 15);
        const float hbsq  = (z2h - gB) + q4.y;      // 0.5 * beta_sq
        const float delta = (q4.x - gB) + gA;
        const float nu    = delta * q4.z;
        qv[i] = fmaf(0.5f * delta, nu, -hbsq) + b2.x;
        const float ns   = nu * q4.w;
        const float eta1 = q4.w - ns;
        const float eta2 = -ns;
        const float u1 = eta1 * fmaf(PHI_C3, eta1 * eta1, PHI_C1);
        const float u2 = eta2 * fmaf(PHI_C3, eta2 * eta2, PHI_C1);
        Dv[i] = fmaxf(tanh_approx(u1) - tanh_approx(u2), 2e-16f);
    }
    #pragma unroll
    for (int i = 0; i < 5; ++i) m = fmaxf(m, qv[i]);

    // warp max of q
    #pragma unroll
    for (int o = 16; o; o >>= 1) m = fmaxf(m, __shfl_xor_sync(0xffffffffu, m, o));

    // ssum = sum exp(q - m) * D
    float ssum = 0.f;
    #pragma unroll
    for (int i = 0; i < 5; ++i) ssum = fmaf(__expf(qv[i] - m), Dv[i], ssum);

    #pragma unroll
    for (int o = 16; o; o >>= 1) ssum += __shfl_xor_sync(0xffffffffu, ssum, o);

    if (l == 0) rowres[w] = m + __logf(ssum);
    __syncthreads();

    // ---- per-block partial + last-block-done finalize ----
    if (t == 0) {
        float s = 0.f;
        #pragma unroll
        for (int r = 0; r < ROWS_PER_BLK; ++r) s += rowres[r];
        d_partials[blockIdx.x] = s;
        __threadfence();
        const unsigned int ticket = atomicAdd(&d_counter, 1u);
        s_is_last = (ticket == (unsigned)(gridDim.x - 1));
    }
    __syncthreads();

    if (s_is_last) {
        volatile float* vp = d_partials;
        float s = 0.f;
        for (int i = t; i < MAIN_BLOCKS; i += 256) s += vp[i];
        red[t] = s; __syncthreads();
        for (int o = 128; o; o >>= 1) { if (t < o) red[t] += red[t + o]; __syncthreads(); }
        if (t == 0) {
            out[0] = red[0] * (1.0f / (float)NROWS);
            d_counter = 0;                 // reset for next graph replay
        }
    }
}

// ---------------------------------------------------------------------------
extern "C" void kernel_launch(void* const* d_in, const int* in_sizes, int n_in,
                              void* d_out, int out_size)
{
    (void)in_sizes; (void)n_in; (void)out_size;
    const float* z  = (const float*)d_in[0];
    const float* pi = (const float*)d_in[1];
    const float* mu = (const float*)d_in[2];
    float* out = (float*)d_out;

    precompute_kernel<<<17, 256>>>(pi, mu);
    main_kernel<<<MAIN_BLOCKS, 256>>>(z, mu, out);
}

// round 9
// speedup vs baseline: 1.0131x; 1.0066x over previous
#include <cuda_runtime.h>
#include <math.h>

// Problem constants (fixed by the reference)
#define N_K        16
#define C_CAT      136          // 16*17/2 upper-tri pairs
#define C_PAD      160          // padded to 32*5 for a uniform unrolled loop
#define DIM        64
#define MU_PITCH   68           // DIM + 4 pad: rows 16B-aligned (68*4 = 272)
#define NROWS      8192         // 512 * 16
#define ROWS_PER_BLK 16         // 2 rows per warp, 8 warps
#define MAIN_BLOCKS (NROWS / ROWS_PER_BLK)   // 512

#define LOG2PI_F   1.8378770664093453f
#define LN2_F      0.6931471805599453f
// Phi-tanh approx: Phi(x) ~= 0.5*(1+tanh(C1*x + C3*x^3))
#define PHI_C1     0.7978845608028654f
#define PHI_C3     0.03567740813712f

// ---- device scratch (static globals; no allocation) ----
__device__ float4 d_c4[C_PAD];   // {k1, 0.5*mB2, recip, s=sqrt(clip_is)}
__device__ float2 d_cb[C_PAD];   // {base, bitcast(A | B<<8)}
__device__ float  d_partials[MAIN_BLOCKS];
__device__ unsigned int d_counter = 0;

__device__ __forceinline__ float tanh_approx(float x) {
    float r; asm("tanh.approx.f32 %0, %1;" : "=f"(r) : "f"(x)); return r;
}

// ---------------------------------------------------------------------------
// Kernel 1: per-category constants. 17 blocks x 256 thr; one WARP per category.
// Diagonal pairs encoded as heavy categories (k1=0, recip=0 -> nu=0; s=20 ->
// tanh(u1)=1, tanh(u2)=0 -> D=1; base=lp). Slots [136,160) are padding.
// ---------------------------------------------------------------------------
__global__ __launch_bounds__(256) void precompute_kernel(const float* __restrict__ pi,
                                                         const float* __restrict__ mu)
{
    const int t = threadIdx.x;
    const int w = t >> 5, l = t & 31;

    if (blockIdx.x == 0 && t >= C_CAT && t < C_PAD) {
        d_c4[t] = make_float4(0.f, 0.f, 0.f, 20.f);
        d_cb[t] = make_float2(-1e30f, __int_as_float(0));
    }

    // warp-local softmax denominator over the 136 logits
    float v0 = pi[l], v1 = pi[l + 32], v2 = pi[l + 64], v3 = pi[l + 96];
    float v4 = (l < 8) ? pi[128 + l] : -INFINITY;
    float mx = fmaxf(fmaxf(fmaxf(v0, v1), fmaxf(v2, v3)), v4);
    #pragma unroll
    for (int o = 16; o; o >>= 1) mx = fmaxf(mx, __shfl_xor_sync(0xffffffffu, mx, o));
    float sm = __expf(v0 - mx) + __expf(v1 - mx) + __expf(v2 - mx) + __expf(v3 - mx)
             + ((l < 8) ? __expf(v4 - mx) : 0.f);
    #pragma unroll
    for (int o = 16; o; o >>= 1) sm += __shfl_xor_sync(0xffffffffu, sm, o);

    const int c = blockIdx.x * 8 + w;          // category index (< 136 always)

    int A = 0, rem = c;
    while (rem >= (N_K - A)) { rem -= (N_K - A); ++A; }
    const int B = A + rem;

    float invsig = 0.f, k1 = 0.f, mB2 = 0.f;
    #pragma unroll
    for (int h = 0; h < 2; ++h) {
        const int d = l + h * 32;
        const float mb = mu[d * N_K + B];
        const float ma = mu[d * N_K + A];
        const float a  = mb - ma;
        invsig = fmaf(a, a, invsig);
        k1     = fmaf(a, mb, k1);
        mB2    = fmaf(mb, mb, mB2);
    }
    #pragma unroll
    for (int o = 16; o; o >>= 1) {
        invsig += __shfl_xor_sync(0xffffffffu, invsig, o);
        k1     += __shfl_xor_sync(0xffffffffu, k1, o);
        mB2    += __shfl_xor_sync(0xffffffffu, mB2, o);
    }

    if (l == 0) {
        const float e  = __expf(pi[c] - mx);
        const float tp = fminf(fmaxf(e / sm, 1e-16f), 1.0f);
        const float lp = -32.0f * LOG2PI_F + logf(tp);

        float base, recip, s, k1s;
        if (A == B) {
            base = lp; recip = 0.f; s = 20.f; k1s = 0.f;
        } else {
            const float clip_is = fminf(fmaxf(invsig, 1e-12f), 1e30f);
            s     = sqrtf(clip_is);
            base  = lp + 0.5f * (LOG2PI_F - logf(clip_is)) - LN2_F;
            recip = 1.0f / invsig;
            k1s   = k1;
        }
        d_c4[c] = make_float4(k1s, 0.5f * mB2, recip, s);
        d_cb[c] = make_float2(base, __int_as_float(A | (B << 8)));
    }
}

// ---------------------------------------------------------------------------
// Kernel 2: main. 16 rows/block (256 thr), TWO rows per warp.
// All serial chains are 2-way interleaved; mu & constants reused across rows.
// ---------------------------------------------------------------------------
__global__ __launch_bounds__(256) void main_kernel(const float* __restrict__ z,
                                                   const float* __restrict__ mu,
                                                   float* __restrict__ out)
{
    __shared__ float  mu_t[N_K][MU_PITCH];          // transposed mu
    __shared__ float  z_s [ROWS_PER_BLK][DIM];      // 4 KB
    __shared__ float4 c4_s[C_PAD];
    __shared__ float2 cb_s[C_PAD];
    __shared__ float  rowres[ROWS_PER_BLK];
    __shared__ float  red[256];
    __shared__ int    s_is_last;

    const int t = threadIdx.x;
    const int w = t >> 5;        // warp; handles rows 2w, 2w+1
    const int l = t & 31;

    // prefetch both rows' z into registers immediately
    const int row0 = blockIdx.x * ROWS_PER_BLK;
    const float* zp0 = z + (row0 + 2 * w) * DIM;
    const float za0 = zp0[l], za1 = zp0[l + 32];
    const float zb0 = zp0[DIM + l], zb1 = zp0[DIM + l + 32];

    // ---- stage mu (transposed) and constants; barrier not waiting on z ----
    for (int i = t; i < DIM * N_K; i += 256) {
        const int d = i >> 4, k = i & 15;           // mu is [d][k]
        mu_t[k][d] = mu[i];
    }
    for (int i = t; i < C_PAD; i += 256) {
        c4_s[i] = d_c4[i];
        cb_s[i] = d_cb[i];
    }
    __syncthreads();

    // per-warp z staging
    z_s[2 * w][l]          = za0;
    z_s[2 * w][l + 32]     = za1;
    z_s[2 * w + 1][l]      = zb0;
    z_s[2 * w + 1][l + 32] = zb1;
    __syncwarp();

    // hoist this lane's 5 category-constant sets (shared by both rows)
    float4 c4r[5];
    float2 cbr[5];
    #pragma unroll
    for (int i = 0; i < 5; ++i) {
        c4r[i] = c4_s[l + 32 * i];
        cbr[i] = cb_s[l + 32 * i];
    }

    // 0.5*|z|^2, both rows interleaved through one butterfly
    float p0 = za0 * za0 + za1 * za1;
    float p1 = zb0 * zb0 + zb1 * zb1;
    #pragma unroll
    for (int o = 16; o; o >>= 1) {
        p0 += __shfl_xor_sync(0xffffffffu, p0, o);
        p1 += __shfl_xor_sync(0xffffffffu, p1, o);
    }
    const float z2h0 = 0.5f * p0;
    const float z2h1 = 0.5f * p1;

    // g-dot for both rows: mu loaded once, z rows broadcast from smem
    float gv0, gv1;
    {
        const int k = l & 15, h = l >> 4;
        const float4* mr  = (const float4*)&mu_t[k][h * 32];
        const float4* zr0 = (const float4*)&z_s[2 * w][h * 32];
        const float4* zr1 = (const float4*)&z_s[2 * w + 1][h * 32];
        float a0 = 0.f, a1 = 0.f, a2 = 0.f, a3 = 0.f;
        float b0 = 0.f, b1 = 0.f, b2 = 0.f, b3 = 0.f;
        #pragma unroll
        for (int j = 0; j < 8; ++j) {
            const float4 mv  = mr[j];
            const float4 zv0 = zr0[j];
            const float4 zv1 = zr1[j];
            a0 = fmaf(zv0.x, mv.x, a0);
            a1 = fmaf(zv0.y, mv.y, a1);
            a2 = fmaf(zv0.z, mv.z, a2);
            a3 = fmaf(zv0.w, mv.w, a3);
            b0 = fmaf(zv1.x, mv.x, b0);
            b1 = fmaf(zv1.y, mv.y, b1);
            b2 = fmaf(zv1.z, mv.z, b2);
            b3 = fmaf(zv1.w, mv.w, b3);
        }
        float acc0 = (a0 + a1) + (a2 + a3);
        float acc1 = (b0 + b1) + (b2 + b3);
        acc0 += __shfl_xor_sync(0xffffffffu, acc0, 16);
        acc1 += __shfl_xor_sync(0xffffffffu, acc1, 16);
        gv0 = acc0;              // lane l and l+16 hold g_{l&15} (row 2w)
        gv1 = acc1;              // (row 2w+1)
    }

    // ---- uniform hot loop: 5 categories x 2 rows = 10 independent chains ----
    float q0[5], q1[5], D0[5], D1[5];
    #pragma unroll
    for (int i = 0; i < 5; ++i) {
        const float4 q4 = c4r[i];                   // k1, 0.5*mB2, recip, s
        const float2 b2 = cbr[i];
        const int ab = __float_as_int(b2.y);
        const int Ai = ab & 15, Bi = (ab >> 8) & 15;
        const float gA0 = __shfl_sync(0xffffffffu, gv0, Ai);
        const float gB0 = __shfl_sync(0xffffffffu, gv0, Bi);
        const float gA1 = __shfl_sync(0xffffffffu, gv1, Ai);
        const float gB1 = __shfl_sync(0xffffffffu, gv1, Bi);

        // row 0
        {
            const float hbsq  = (z2h0 - gB0) + q4.y;
            const float delta = (q4.x - gB0) + gA0;
            const float nu    = delta * q4.z;
            q0[i] = fmaf(0.5f * delta, nu, -hbsq) + b2.x;
            const float ns   = nu * q4.w;
            const float eta1 = q4.w - ns;
            const float eta2 = -ns;
            const float u1 = eta1 * fmaf(PHI_C3, eta1 * eta1, PHI_C1);
            const float u2 = eta2 * fmaf(PHI_C3, eta2 * eta2, PHI_C1);
            D0[i] = fmaxf(tanh_approx(u1) - tanh_approx(u2), 2e-16f);
        }
        // row 1
        {
            const float hbsq  = (z2h1 - gB1) + q4.y;
            const float delta = (q4.x - gB1) + gA1;
            const float nu    = delta * q4.z;
            q1[i] = fmaf(0.5f * delta, nu, -hbsq) + b2.x;
            const float ns   = nu * q4.w;
            const float eta1 = q4.w - ns;
            const float eta2 = -ns;
            const float u1 = eta1 * fmaf(PHI_C3, eta1 * eta1, PHI_C1);
            const float u2 = eta2 * fmaf(PHI_C3, eta2 * eta2, PHI_C1);
            D1[i] = fmaxf(tanh_approx(u1) - tanh_approx(u2), 2e-16f);
        }
    }

    float m0 = -INFINITY, m1 = -INFINITY;
    #pragma unroll
    for (int i = 0; i < 5; ++i) { m0 = fmaxf(m0, q0[i]); m1 = fmaxf(m1, q1[i]); }

    // warp max, both rows interleaved
    #pragma unroll
    for (int o = 16; o; o >>= 1) {
        m0 = fmaxf(m0, __shfl_xor_sync(0xffffffffu, m0, o));
        m1 = fmaxf(m1, __shfl_xor_sync(0xffffffffu, m1, o));
    }

    float s0 = 0.f, s1 = 0.f;
    #pragma unroll
    for (int i = 0; i < 5; ++i) {
        s0 = fmaf(__expf(q0[i] - m0), D0[i], s0);
        s1 = fmaf(__expf(q1[i] - m1), D1[i], s1);
    }

    #pragma unroll
    for (int o = 16; o; o >>= 1) {
        s0 += __shfl_xor_sync(0xffffffffu, s0, o);
        s1 += __shfl_xor_sync(0xffffffffu, s1, o);
    }

    if (l == 0) {
        rowres[2 * w]     = m0 + __logf(s0);
        rowres[2 * w + 1] = m1 + __logf(s1);
    }
    __syncthreads();

    // ---- per-block partial + last-block-done finalize ----
    if (t == 0) {
        float s = 0.f;
        #pragma unroll
        for (int r = 0; r < ROWS_PER_BLK; ++r) s += rowres[r];
        d_partials[blockIdx.x] = s;
        __threadfence();
        const unsigned int ticket = atomicAdd(&d_counter, 1u);
        s_is_last = (ticket == (unsigned)(gridDim.x - 1));
    }
    __syncthreads();

    if (s_is_last) {
        volatile float* vp = d_partials;
        float s = 0.f;
        for (int i = t; i < MAIN_BLOCKS; i += 256) s += vp[i];
        red[t] = s; __syncthreads();
        for (int o = 128; o; o >>= 1) { if (t < o) red[t] += red[t + o]; __syncthreads(); }
        if (t == 0) {
            out[0] = red[0] * (1.0f / (float)NROWS);
            d_counter = 0;                 // reset for next graph replay
        }
    }
}

// ---------------------------------------------------------------------------
extern "C" void kernel_launch(void* const* d_in, const int* in_sizes, int n_in,
                              void* d_out, int out_size)
{
    (void)in_sizes; (void)n_in; (void)out_size;
    const float* z  = (const float*)d_in[0];
    const float* pi = (const float*)d_in[1];
    const float* mu = (const float*)d_in[2];
    float* out = (float*)d_out;

    precompute_kernel<<<17, 256>>>(pi, mu);
    main_kernel<<<MAIN_BLOCKS, 256>>>(z, mu, out);
}

// round 10
// speedup vs baseline: 1.1600x; 1.1450x over previous
#include <cuda_runtime.h>
#include <math.h>

// Problem constants (fixed by the reference)
#define N_K        16
#define C_CAT      136          // 16*17/2 upper-tri pairs
#define C_PAD      160          // padded to 32*5 for a uniform unrolled loop
#define DIM        64
#define MU_PITCH   68           // DIM + 4 pad: rows 16B-aligned (68*4 = 272)
#define NROWS      8192         // 512 * 16
#define ROWS_PER_BLK 16         // 2 rows per warp, 8 warps
#define MAIN_BLOCKS (NROWS / ROWS_PER_BLK)   // 512

#define LOG2PI_F   1.8378770664093453f
#define LN2_F      0.6931471805599453f
// Phi-tanh approx: Phi(x) ~= 0.5*(1+tanh(C1*x + C3*x^3))
#define PHI_C1     0.7978845608028654f
#define PHI_C3     0.03567740813712f

// ---- device scratch (static globals; no allocation) ----
__device__ float  d_partials[MAIN_BLOCKS];
__device__ unsigned int d_counter = 0;

__device__ __forceinline__ float tanh_approx(float x) {
    float r; asm("tanh.approx.f32 %0, %1;" : "=f"(r) : "f"(x)); return r;
}

// ---------------------------------------------------------------------------
// SINGLE fused kernel. 16 rows/block (256 thr), two rows per warp.
// Per-block redundant constant prologue (cheap: warp-local softmax w/o logs,
// Gram-based category constants, 2 block syncs), then main math, then
// last-block-done deterministic finalize.
// Diagonal pairs encoded as heavy categories (k1=0, recip=0 -> nu=0; s=20 ->
// tanh(u1)=1, tanh(u2)=0 -> D=1; base=lp). Slots [136,160) are -inf padding.
// ---------------------------------------------------------------------------
__global__ __launch_bounds__(256) void fused_kernel(const float* __restrict__ z,
                                                    const float* __restrict__ pi,
                                                    const float* __restrict__ mu,
                                                    float* __restrict__ out)
{
    __shared__ float  mu_t[N_K][MU_PITCH];          // transposed mu
    __shared__ float  z_s [ROWS_PER_BLK][DIM];      // 4 KB
    __shared__ float4 c4_s[C_PAD];                  // {k1, 0.5*mB2, recip, s}
    __shared__ float2 cb_s[C_PAD];                  // {base, bitcast(A|B<<8)}
    __shared__ float  rowres[ROWS_PER_BLK];
    __shared__ float  red[256];
    __shared__ int    s_is_last;

    const int t = threadIdx.x;
    const int w = t >> 5;        // warp; handles rows 2w, 2w+1
    const int l = t & 31;

    // prefetch both rows' z into registers immediately (DRAM latency overlaps
    // the whole prologue below)
    const int row0 = blockIdx.x * ROWS_PER_BLK;
    const float* zp0 = z + (row0 + 2 * w) * DIM;
    const float za0 = zp0[l], za1 = zp0[l + 32];
    const float zb0 = zp0[DIM + l], zb1 = zp0[DIM + l + 32];

    // stage mu transposed
    for (int i = t; i < DIM * N_K; i += 256) {
        const int d = i >> 4, k = i & 15;           // mu is [d][k]
        mu_t[k][d] = mu[i];
    }
    // stage this warp's z rows (read only by this warp later)
    z_s[2 * w][l]          = za0;
    z_s[2 * w][l + 32]     = za1;
    z_s[2 * w + 1][l]      = zb0;
    z_s[2 * w + 1][l + 32] = zb1;

    // padding category slots
    if (t >= C_CAT && t < C_PAD) {
        c4_s[t] = make_float4(0.f, 0.f, 0.f, 20.f);
        cb_s[t] = make_float2(-1e30f, __int_as_float(0));
    }

    // warp-local softmax denominator over the 136 pi logits (registers only)
    const float v0 = pi[l], v1 = pi[l + 32], v2 = pi[l + 64], v3 = pi[l + 96];
    const float v4 = (l < 8) ? pi[128 + l] : -INFINITY;
    float mx = fmaxf(fmaxf(fmaxf(v0, v1), fmaxf(v2, v3)), v4);
    #pragma unroll
    for (int o = 16; o; o >>= 1) mx = fmaxf(mx, __shfl_xor_sync(0xffffffffu, mx, o));
    float sm = __expf(v0 - mx) + __expf(v1 - mx) + __expf(v2 - mx) + __expf(v3 - mx)
             + ((l < 8) ? __expf(v4 - mx) : 0.f);
    #pragma unroll
    for (int o = 16; o; o >>= 1) sm += __shfl_xor_sync(0xffffffffu, sm, o);
    const float lgden = mx + __logf(sm);            // log softmax denominator

    __syncthreads();                                 // mu_t ready

    // ---- per-category constants: thread t <-> category t (t < 136) ----
    if (t < C_CAT) {
        // decode (A,B) from upper-tri row-major index
        int A = 0, rem = t;
        while (rem >= (N_K - A)) { rem -= (N_K - A); ++A; }
        const int B = A + rem;

        // Gram entries GAA, GAB, GBB in one float4 pass (12-way acc ILP)
        const float4* ma = (const float4*)&mu_t[A][0];
        const float4* mb = (const float4*)&mu_t[B][0];
        float aa0=0.f, aa1=0.f, aa2=0.f, aa3=0.f;
        float ab0=0.f, ab1=0.f, ab2=0.f, ab3=0.f;
        float bb0=0.f, bb1=0.f, bb2=0.f, bb3=0.f;
        #pragma unroll
        for (int j = 0; j < 16; ++j) {
            const float4 fa = ma[j];
            const float4 fb = mb[j];
            aa0 = fmaf(fa.x, fa.x, aa0); aa1 = fmaf(fa.y, fa.y, aa1);
            aa2 = fmaf(fa.z, fa.z, aa2); aa3 = fmaf(fa.w, fa.w, aa3);
            ab0 = fmaf(fa.x, fb.x, ab0); ab1 = fmaf(fa.y, fb.y, ab1);
            ab2 = fmaf(fa.z, fb.z, ab2); ab3 = fmaf(fa.w, fb.w, ab3);
            bb0 = fmaf(fb.x, fb.x, bb0); bb1 = fmaf(fb.y, fb.y, bb1);
            bb2 = fmaf(fb.z, fb.z, bb2); bb3 = fmaf(fb.w, fb.w, bb3);
        }
        const float GAA = (aa0 + aa1) + (aa2 + aa3);
        const float GAB = (ab0 + ab1) + (ab2 + ab3);
        const float GBB = (bb0 + bb1) + (bb2 + bb3);

        const float invsig = (GAA - 2.0f * GAB) + GBB;
        // this thread's pi logit was already loaded: t = l + 32*w
        const float my_pi = (w == 0) ? v0 : (w == 1) ? v1 : (w == 2) ? v2
                          : (w == 3) ? v3 : v4;
        const float lp = -32.0f * LOG2PI_F + (my_pi - lgden);  // log temp_pi term

        float base, recip, s, k1;
        if (A == B) {                        // diag: inv_sig == 0 exactly
            base = lp; recip = 0.f; s = 20.f; k1 = 0.f;
        } else {
            const float clip_is = fminf(fmaxf(invsig, 1e-12f), 1e30f);
            s     = sqrtf(clip_is);
            base  = lp + 0.5f * (LOG2PI_F - __logf(clip_is)) - LN2_F;
            recip = 1.0f / invsig;
            k1    = GBB - GAB;               // dot(alpha, mu_B)
        }
        c4_s[t] = make_float4(k1, 0.5f * GBB, recip, s);
        cb_s[t] = make_float2(base, __int_as_float(A | (B << 8)));
    }
    __syncthreads();                                 // constants ready

    // hoist this lane's 5 category-constant sets (shared by both rows)
    float4 c4r[5];
    float2 cbr[5];
    #pragma unroll
    for (int i = 0; i < 5; ++i) {
        c4r[i] = c4_s[l + 32 * i];
        cbr[i] = cb_s[l + 32 * i];
    }

    // 0.5*|z|^2, both rows interleaved through one butterfly
    float p0 = za0 * za0 + za1 * za1;
    float p1 = zb0 * zb0 + zb1 * zb1;
    #pragma unroll
    for (int o = 16; o; o >>= 1) {
        p0 += __shfl_xor_sync(0xffffffffu, p0, o);
        p1 += __shfl_xor_sync(0xffffffffu, p1, o);
    }
    const float z2h0 = 0.5f * p0;
    const float z2h1 = 0.5f * p1;

    // g-dot for both rows: mu loaded once, z rows broadcast from smem
    float gv0, gv1;
    {
        const int k = l & 15, h = l >> 4;
        const float4* mr  = (const float4*)&mu_t[k][h * 32];
        const float4* zr0 = (const float4*)&z_s[2 * w][h * 32];
        const float4* zr1 = (const float4*)&z_s[2 * w + 1][h * 32];
        float a0 = 0.f, a1 = 0.f, a2 = 0.f, a3 = 0.f;
        float b0 = 0.f, b1 = 0.f, b2 = 0.f, b3 = 0.f;
        #pragma unroll
        for (int j = 0; j < 8; ++j) {
            const float4 mv  = mr[j];
            const float4 zv0 = zr0[j];
            const float4 zv1 = zr1[j];
            a0 = fmaf(zv0.x, mv.x, a0);
            a1 = fmaf(zv0.y, mv.y, a1);
            a2 = fmaf(zv0.z, mv.z, a2);
            a3 = fmaf(zv0.w, mv.w, a3);
            b0 = fmaf(zv1.x, mv.x, b0);
            b1 = fmaf(zv1.y, mv.y, b1);
            b2 = fmaf(zv1.z, mv.z, b2);
            b3 = fmaf(zv1.w, mv.w, b3);
        }
        float acc0 = (a0 + a1) + (a2 + a3);
        float acc1 = (b0 + b1) + (b2 + b3);
        acc0 += __shfl_xor_sync(0xffffffffu, acc0, 16);
        acc1 += __shfl_xor_sync(0xffffffffu, acc1, 16);
        gv0 = acc0;              // lane l and l+16 hold g_{l&15} (row 2w)
        gv1 = acc1;              // (row 2w+1)
    }

    // ---- uniform hot loop: 5 categories x 2 rows = 10 independent chains ----
    float q0[5], q1[5], D0[5], D1[5];
    #pragma unroll
    for (int i = 0; i < 5; ++i) {
        const float4 q4 = c4r[i];                   // k1, 0.5*mB2, recip, s
        const float2 b2 = cbr[i];
        const int ab = __float_as_int(b2.y);
        const int Ai = ab & 15, Bi = (ab >> 8) & 15;
        const float gA0 = __shfl_sync(0xffffffffu, gv0, Ai);
        const float gB0 = __shfl_sync(0xffffffffu, gv0, Bi);
        const float gA1 = __shfl_sync(0xffffffffu, gv1, Ai);
        const float gB1 = __shfl_sync(0xffffffffu, gv1, Bi);

        // row 0
        {
            const float hbsq  = (z2h0 - gB0) + q4.y;
            const float delta = (q4.x - gB0) + gA0;
            const float nu    = delta * q4.z;
            q0[i] = fmaf(0.5f * delta, nu, -hbsq) + b2.x;
            const float ns   = nu * q4.w;
            const float eta1 = q4.w - ns;
            const float eta2 = -ns;
            const float u1 = eta1 * fmaf(PHI_C3, eta1 * eta1, PHI_C1);
            const float u2 = eta2 * fmaf(PHI_C3, eta2 * eta2, PHI_C1);
            D0[i] = fmaxf(tanh_approx(u1) - tanh_approx(u2), 2e-16f);
        }
        // row 1
        {
            const float hbsq  = (z2h1 - gB1) + q4.y;
            const float delta = (q4.x - gB1) + gA1;
            const float nu    = delta * q4.z;
            q1[i] = fmaf(0.5f * delta, nu, -hbsq) + b2.x;
            const float ns   = nu * q4.w;
            const float eta1 = q4.w - ns;
            const float eta2 = -ns;
            const float u1 = eta1 * fmaf(PHI_C3, eta1 * eta1, PHI_C1);
            const float u2 = eta2 * fmaf(PHI_C3, eta2 * eta2, PHI_C1);
            D1[i] = fmaxf(tanh_approx(u1) - tanh_approx(u2), 2e-16f);
        }
    }

    float m0 = -INFINITY, m1 = -INFINITY;
    #pragma unroll
    for (int i = 0; i < 5; ++i) { m0 = fmaxf(m0, q0[i]); m1 = fmaxf(m1, q1[i]); }

    // warp max, both rows interleaved
    #pragma unroll
    for (int o = 16; o; o >>= 1) {
        m0 = fmaxf(m0, __shfl_xor_sync(0xffffffffu, m0, o));
        m1 = fmaxf(m1, __shfl_xor_sync(0xffffffffu, m1, o));
    }

    float s0 = 0.f, s1 = 0.f;
    #pragma unroll
    for (int i = 0; i < 5; ++i) {
        s0 = fmaf(__expf(q0[i] - m0), D0[i], s0);
        s1 = fmaf(__expf(q1[i] - m1), D1[i], s1);
    }

    #pragma unroll
    for (int o = 16; o; o >>= 1) {
        s0 += __shfl_xor_sync(0xffffffffu, s0, o);
        s1 += __shfl_xor_sync(0xffffffffu, s1, o);
    }

    if (l == 0) {
        rowres[2 * w]     = m0 + __logf(s0);
        rowres[2 * w + 1] = m1 + __logf(s1);
    }
    __syncthreads();

    // ---- per-block partial + last-block-done finalize ----
    if (t == 0) {
        float s = 0.f;
        #pragma unroll
        for (int r = 0; r < ROWS_PER_BLK; ++r) s += rowres[r];
        d_partials[blockIdx.x] = s;
        __threadfence();
        const unsigned int ticket = atomicAdd(&d_counter, 1u);
        s_is_last = (ticket == (unsigned)(gridDim.x - 1));
    }
    __syncthreads();

    if (s_is_last) {
        volatile float* vp = d_partials;
        float s = 0.f;
        for (int i = t; i < MAIN_BLOCKS; i += 256) s += vp[i];
        red[t] = s; __syncthreads();
        for (int o = 128; o; o >>= 1) { if (t < o) red[t] += red[t + o]; __syncthreads(); }
        if (t == 0) {
            out[0] = red[0] * (1.0f / (float)NROWS);
            d_counter = 0;                 // reset for next graph replay
        }
    }
}

// ---------------------------------------------------------------------------
extern "C" void kernel_launch(void* const* d_in, const int* in_sizes, int n_in,
                              void* d_out, int out_size)
{
    (void)in_sizes; (void)n_in; (void)out_size;
    const float* z  = (const float*)d_in[0];
    const float* pi = (const float*)d_in[1];
    const float* mu = (const float*)d_in[2];
    float* out = (float*)d_out;

    fused_kernel<<<MAIN_BLOCKS, 256>>>(z, pi, mu, out);
}